// round 2
// baseline (speedup 1.0000x reference)
#include <cuda_runtime.h>
#include <cuda_bf16.h>
#include <cstdint>

// ---------------------------------------------------------------------------
// Problem constants
// ---------------------------------------------------------------------------
#define B_ROWS 4096
#define N_DIM  1024
#define P_DIM  32
#define E_DIM  16
#define C_DIM  (N_DIM * E_DIM)   /* 16384 output columns (i*16+e) */
#define KSPLIT (3 * N_DIM)       /* 3072: [hi*hi | hi*lo | lo*hi] */

// GEMM tiling (mma.sync path — tcgen05 unavailable on compute_103 vtarget)
#define BM 128
#define BN 256
#define BK 64                       /* bf16 elems per K-chunk (128B rows) */
#define NCHUNK (KSPLIT / BK)        /* 48 */
#define NSTAGES 4
#define STAGE_A_BYTES (BM * 128)    /* 16 KB */
#define STAGE_B_BYTES (BN * 128)    /* 32 KB */
#define STAGE_BYTES (STAGE_A_BYTES + STAGE_B_BYTES)
#define SMEM_DYN (NSTAGES * STAGE_BYTES)   /* 192 KB */
#define NTHREADS 512

// ---------------------------------------------------------------------------
// Device scratch (allocation-free rule: __device__ globals)
// ---------------------------------------------------------------------------
__device__ __align__(16) __nv_bfloat16 g_A[(size_t)B_ROWS * KSPLIT];   // 24 MB
__device__ __align__(16) __nv_bfloat16 g_Bm[(size_t)C_DIM * KSPLIT];   // 96 MB

// ---------------------------------------------------------------------------
// PTX helpers (baseline features only — must compile for compute_103)
// ---------------------------------------------------------------------------
__device__ __forceinline__ uint32_t cvta_shared(const void* p) {
    return (uint32_t)__cvta_generic_to_shared(p);
}

__device__ __forceinline__ void cp_async16(uint32_t dst, const void* src) {
    asm volatile("cp.async.cg.shared.global [%0], [%1], 16;\n"
                 :: "r"(dst), "l"(src) : "memory");
}

__device__ __forceinline__ void ldmatrix_x4(uint32_t* d, uint32_t addr) {
    asm volatile("ldmatrix.sync.aligned.m8n8.x4.shared.b16 {%0,%1,%2,%3}, [%4];"
                 : "=r"(d[0]), "=r"(d[1]), "=r"(d[2]), "=r"(d[3]) : "r"(addr));
}

__device__ __forceinline__ void mma_bf16(float* c, const uint32_t* a,
                                         uint32_t b0, uint32_t b1) {
    asm volatile("mma.sync.aligned.m16n8k16.row.col.f32.bf16.bf16.f32 "
                 "{%0,%1,%2,%3}, {%4,%5,%6,%7}, {%8,%9}, {%0,%1,%2,%3};"
                 : "+f"(c[0]), "+f"(c[1]), "+f"(c[2]), "+f"(c[3])
                 : "r"(a[0]), "r"(a[1]), "r"(a[2]), "r"(a[3]),
                   "r"(b0), "r"(b1));
}

__device__ __forceinline__ uint32_t sw128(uint32_t off) {
    return off ^ ((off >> 3) & 0x70);
}

// ---------------------------------------------------------------------------
// Kernel 1: split x[4096,1024] fp32 -> A' = [x_hi | x_hi | x_lo] bf16
// ---------------------------------------------------------------------------
__global__ void split_x_kernel(const float* __restrict__ x) {
    int t = blockIdx.x * blockDim.x + threadIdx.x;
    int idx4 = t << 2;
    int b = idx4 >> 10;
    int j = idx4 & (N_DIM - 1);
    float4 v = *reinterpret_cast<const float4*>(x + idx4);

    __nv_bfloat16 h0 = __float2bfloat16(v.x);
    __nv_bfloat16 h1 = __float2bfloat16(v.y);
    __nv_bfloat16 h2 = __float2bfloat16(v.z);
    __nv_bfloat16 h3 = __float2bfloat16(v.w);
    __nv_bfloat16 l0 = __float2bfloat16(v.x - __bfloat162float(h0));
    __nv_bfloat16 l1 = __float2bfloat16(v.y - __bfloat162float(h1));
    __nv_bfloat16 l2 = __float2bfloat16(v.z - __bfloat162float(h2));
    __nv_bfloat16 l3 = __float2bfloat16(v.w - __bfloat162float(h3));

    ushort4 hv, lv;
    hv.x = __bfloat16_as_ushort(h0); hv.y = __bfloat16_as_ushort(h1);
    hv.z = __bfloat16_as_ushort(h2); hv.w = __bfloat16_as_ushort(h3);
    lv.x = __bfloat16_as_ushort(l0); lv.y = __bfloat16_as_ushort(l1);
    lv.z = __bfloat16_as_ushort(l2); lv.w = __bfloat16_as_ushort(l3);

    size_t base = (size_t)b * KSPLIT + j;
    *reinterpret_cast<ushort4*>(g_A + base)           = hv;   // seg0: x_hi
    *reinterpret_cast<ushort4*>(g_A + base + N_DIM)   = hv;   // seg1: x_hi
    *reinterpret_cast<ushort4*>(g_A + base + 2*N_DIM) = lv;   // seg2: x_lo
}

// ---------------------------------------------------------------------------
// Kernel 2: filters[e,i,j] = sum_p params[p,e]*T[p,i,j], stored as
//           B'[c=i*16+e, k] = [W_hi | W_lo | W_hi] bf16  (K-major rows)
// ---------------------------------------------------------------------------
__global__ void build_filters_kernel(const float* __restrict__ params,
                                     const float* __restrict__ T) {
    __shared__ float sp[P_DIM * E_DIM];
    for (int s = threadIdx.x; s < P_DIM * E_DIM; s += blockDim.x) sp[s] = params[s];
    __syncthreads();

    int t = blockIdx.x * blockDim.x + threadIdx.x;
    int idx4 = t << 2;
    int i = idx4 >> 10;
    int j = idx4 & (N_DIM - 1);

    float4 acc[E_DIM];
#pragma unroll
    for (int e = 0; e < E_DIM; e++) acc[e] = make_float4(0.f, 0.f, 0.f, 0.f);

    for (int p = 0; p < P_DIM; p++) {
        float4 tv = *reinterpret_cast<const float4*>(T + ((size_t)p << 20) + idx4);
#pragma unroll
        for (int e = 0; e < E_DIM; e++) {
            float w = sp[p * E_DIM + e];
            acc[e].x = fmaf(tv.x, w, acc[e].x);
            acc[e].y = fmaf(tv.y, w, acc[e].y);
            acc[e].z = fmaf(tv.z, w, acc[e].z);
            acc[e].w = fmaf(tv.w, w, acc[e].w);
        }
    }

#pragma unroll
    for (int e = 0; e < E_DIM; e++) {
        int c = i * E_DIM + e;
        size_t base = (size_t)c * KSPLIT + j;
        __nv_bfloat16 h0 = __float2bfloat16(acc[e].x);
        __nv_bfloat16 h1 = __float2bfloat16(acc[e].y);
        __nv_bfloat16 h2 = __float2bfloat16(acc[e].z);
        __nv_bfloat16 h3 = __float2bfloat16(acc[e].w);
        __nv_bfloat16 l0 = __float2bfloat16(acc[e].x - __bfloat162float(h0));
        __nv_bfloat16 l1 = __float2bfloat16(acc[e].y - __bfloat162float(h1));
        __nv_bfloat16 l2 = __float2bfloat16(acc[e].z - __bfloat162float(h2));
        __nv_bfloat16 l3 = __float2bfloat16(acc[e].w - __bfloat162float(h3));
        ushort4 hv, lv;
        hv.x = __bfloat16_as_ushort(h0); hv.y = __bfloat16_as_ushort(h1);
        hv.z = __bfloat16_as_ushort(h2); hv.w = __bfloat16_as_ushort(h3);
        lv.x = __bfloat16_as_ushort(l0); lv.y = __bfloat16_as_ushort(l1);
        lv.z = __bfloat16_as_ushort(l2); lv.w = __bfloat16_as_ushort(l3);
        *reinterpret_cast<ushort4*>(g_Bm + base)           = hv;  // seg0: W_hi
        *reinterpret_cast<ushort4*>(g_Bm + base + N_DIM)   = lv;  // seg1: W_lo
        *reinterpret_cast<ushort4*>(g_Bm + base + 2*N_DIM) = hv;  // seg2: W_hi
    }
}

// ---------------------------------------------------------------------------
// Kernel 3: GEMM out[b,c] = sum_k A'[b,k]*B'[c,k], then swish, fp32 out.
// CTA 128x256, K chunks of 64, 4-stage cp.async pipeline, mma.sync bf16.
// 16 warps: warp grid 4(M) x 4(N), warp tile 32x64.
// ---------------------------------------------------------------------------
__device__ __forceinline__ void load_chunk(uint32_t sbase, int tid, int kc,
                                           const __nv_bfloat16* __restrict__ Ag,
                                           const __nv_bfloat16* __restrict__ Bg) {
    int st = kc & (NSTAGES - 1);
    uint32_t stA = sbase + st * STAGE_BYTES;
    uint32_t stB = stA + STAGE_A_BYTES;
    const __nv_bfloat16* ga = Ag + kc * BK;
    const __nv_bfloat16* gb = Bg + kc * BK;
#pragma unroll
    for (int i = 0; i < 2; i++) {               // A: 128 rows x 8 vec16 = 1024
        int v = i * NTHREADS + tid;
        int row = v >> 3, c16 = v & 7;
        uint32_t off = (uint32_t)(row * 128 + c16 * 16);
        cp_async16(stA + sw128(off), ga + (size_t)row * KSPLIT + (c16 << 3));
    }
#pragma unroll
    for (int i = 0; i < 4; i++) {               // B: 256 rows x 8 vec16 = 2048
        int v = i * NTHREADS + tid;
        int row = v >> 3, c16 = v & 7;
        uint32_t off = (uint32_t)(row * 128 + c16 * 16);
        cp_async16(stB + sw128(off), gb + (size_t)row * KSPLIT + (c16 << 3));
    }
    asm volatile("cp.async.commit_group;\n" ::: "memory");
}

__global__ void __launch_bounds__(NTHREADS, 1)
gemm_swish_kernel(float* __restrict__ out) {
    extern __shared__ char dsm[];
    const int tid  = threadIdx.x;
    const int wid  = tid >> 5;
    const int lane = tid & 31;
    const int warp_m = wid & 3;     // 0..3 -> 32-row slices
    const int warp_n = wid >> 2;    // 0..3 -> 64-col slices

    uint32_t sbase = cvta_shared(dsm);

    const size_t m_base = (size_t)blockIdx.x * BM;
    const size_t n_base = (size_t)blockIdx.y * BN;
    const __nv_bfloat16* __restrict__ Ag = g_A  + m_base * KSPLIT;
    const __nv_bfloat16* __restrict__ Bg = g_Bm + n_base * KSPLIT;

    float acc[2][8][4];
#pragma unroll
    for (int mi = 0; mi < 2; mi++)
#pragma unroll
        for (int ni = 0; ni < 8; ni++)
#pragma unroll
            for (int c = 0; c < 4; c++) acc[mi][ni][c] = 0.0f;

    // prologue: stages 0..2 in flight
    load_chunk(sbase, tid, 0, Ag, Bg);
    load_chunk(sbase, tid, 1, Ag, Bg);
    load_chunk(sbase, tid, 2, Ag, Bg);

    // per-lane ldmatrix row offsets (row part of the address is fixed)
    const int a_row = warp_m * 32 + (lane & 15);            // + mi*16
    const int a_kh  = (lane >> 4) << 4;                     // 0 or 16 bytes
    const int b_row = warp_n * 64 + (lane & 7) + ((lane & 16) >> 1);  // + ni*16
    const int b_kh  = (lane & 8) << 1;                      // 0 or 16 bytes

    for (int k = 0; k < NCHUNK; k++) {
        if (k < NCHUNK - 2)       asm volatile("cp.async.wait_group 2;\n" ::: "memory");
        else if (k == NCHUNK - 2) asm volatile("cp.async.wait_group 1;\n" ::: "memory");
        else                      asm volatile("cp.async.wait_group 0;\n" ::: "memory");
        __syncthreads();

        if (k + 3 < NCHUNK) load_chunk(sbase, tid, k + 3, Ag, Bg);

        int st = k & (NSTAGES - 1);
        uint32_t stA = sbase + st * STAGE_BYTES;
        uint32_t stB = stA + STAGE_A_BYTES;

#pragma unroll
        for (int kk = 0; kk < 4; kk++) {        // 4 x k16 per 64-chunk
            uint32_t a[2][4];
#pragma unroll
            for (int mi = 0; mi < 2; mi++) {
                uint32_t off = (uint32_t)((a_row + mi * 16) * 128 + kk * 32 + a_kh);
                ldmatrix_x4(a[mi], stA + sw128(off));
            }
            uint32_t b[4][4];
#pragma unroll
            for (int ni = 0; ni < 4; ni++) {
                uint32_t off = (uint32_t)((b_row + ni * 16) * 128 + kk * 32 + b_kh);
                ldmatrix_x4(b[ni], stB + sw128(off));
            }
#pragma unroll
            for (int mi = 0; mi < 2; mi++)
#pragma unroll
                for (int n8 = 0; n8 < 8; n8++)
                    mma_bf16(acc[mi][n8], a[mi],
                             b[n8 >> 1][(n8 & 1) * 2],
                             b[n8 >> 1][(n8 & 1) * 2 + 1]);
        }
    }

    // epilogue: swish + store fp32
    const int quad = lane >> 2;        // 0..7: row within 8-row group
    const int tcol = (lane & 3) * 2;   // col pair
#pragma unroll
    for (int mi = 0; mi < 2; mi++) {
        size_t row0 = m_base + warp_m * 32 + mi * 16 + quad;
#pragma unroll
        for (int n8 = 0; n8 < 8; n8++) {
            size_t col = n_base + warp_n * 64 + n8 * 8 + tcol;
            float a0 = acc[mi][n8][0], a1 = acc[mi][n8][1];
            float a2 = acc[mi][n8][2], a3 = acc[mi][n8][3];
            float2 v0, v1;
            v0.x = a0 / (1.0f + __expf(-a0));
            v0.y = a1 / (1.0f + __expf(-a1));
            v1.x = a2 / (1.0f + __expf(-a2));
            v1.y = a3 / (1.0f + __expf(-a3));
            *reinterpret_cast<float2*>(out + row0 * C_DIM + col)       = v0;
            *reinterpret_cast<float2*>(out + (row0 + 8) * C_DIM + col) = v1;
        }
    }
}

// ---------------------------------------------------------------------------
// Launch
// ---------------------------------------------------------------------------
extern "C" void kernel_launch(void* const* d_in, const int* in_sizes, int n_in,
                              void* d_out, int out_size) {
    const float* x = nullptr;
    const float* params = nullptr;
    const float* T = nullptr;
    for (int i = 0; i < n_in; i++) {
        if (in_sizes[i] == B_ROWS * N_DIM)             x      = (const float*)d_in[i];
        else if (in_sizes[i] == P_DIM * E_DIM)         params = (const float*)d_in[i];
        else if (in_sizes[i] == P_DIM * N_DIM * N_DIM) T      = (const float*)d_in[i];
    }
    float* out = (float*)d_out;

    split_x_kernel<<<(B_ROWS * N_DIM) / (256 * 4), 256>>>(x);
    build_filters_kernel<<<(N_DIM * N_DIM) / (256 * 4), 256>>>(params, T);

    cudaFuncSetAttribute(gemm_swish_kernel,
                         cudaFuncAttributeMaxDynamicSharedMemorySize, SMEM_DYN);
    gemm_swish_kernel<<<dim3(B_ROWS / BM, C_DIM / BN), NTHREADS, SMEM_DYN>>>(out);
}

// round 3
// speedup vs baseline: 1.4110x; 1.4110x over previous
#include <cuda_runtime.h>
#include <cuda_fp16.h>
#include <cstdint>

// ---------------------------------------------------------------------------
// Problem constants
// ---------------------------------------------------------------------------
#define B_ROWS 4096
#define N_DIM  1024
#define P_DIM  32
#define E_DIM  16
#define C_DIM  (N_DIM * E_DIM)   /* 16384 output columns (i*16+e) */
#define KA     2048              /* A K-dim: [x_hi | x_lo] fp16 */
#define KB     1024              /* B K-dim: W_hi fp16 (reused by both A segs) */

// GEMM tiling (mma.sync path — tcgen05 unavailable on compute_103 vtarget)
#define BM 128
#define BN 256
#define BK 64                        /* fp16 elems per K-chunk (128B rows) */
#define NCH (KB / BK)                /* 16 B-chunks; each paired with 2 A-chunks */
#define NSTAGES 3
#define STAGE_AH_BYTES (BM * 128)    /* A_hi 16 KB */
#define STAGE_A_BYTES  (2 * STAGE_AH_BYTES)  /* A_hi + A_lo 32 KB */
#define STAGE_B_BYTES  (BN * 128)    /* 32 KB */
#define STAGE_BYTES (STAGE_A_BYTES + STAGE_B_BYTES)   /* 64 KB */
#define SMEM_DYN (NSTAGES * STAGE_BYTES)              /* 192 KB */
#define NTHREADS 512

// ---------------------------------------------------------------------------
// Device scratch (allocation-free rule: __device__ globals)
// ---------------------------------------------------------------------------
__device__ __align__(16) __half g_A[(size_t)B_ROWS * KA];   // 16 MB
__device__ __align__(16) __half g_Bm[(size_t)C_DIM * KB];   // 32 MB

// ---------------------------------------------------------------------------
// PTX helpers (baseline features only — must compile for compute_103)
// ---------------------------------------------------------------------------
__device__ __forceinline__ uint32_t cvta_shared(const void* p) {
    return (uint32_t)__cvta_generic_to_shared(p);
}

__device__ __forceinline__ void cp_async16(uint32_t dst, const void* src) {
    asm volatile("cp.async.cg.shared.global [%0], [%1], 16;\n"
                 :: "r"(dst), "l"(src) : "memory");
}

__device__ __forceinline__ void ldmatrix_x4(uint32_t* d, uint32_t addr) {
    asm volatile("ldmatrix.sync.aligned.m8n8.x4.shared.b16 {%0,%1,%2,%3}, [%4];"
                 : "=r"(d[0]), "=r"(d[1]), "=r"(d[2]), "=r"(d[3]) : "r"(addr));
}

__device__ __forceinline__ void mma_f16(float* c, const uint32_t* a,
                                        uint32_t b0, uint32_t b1) {
    asm volatile("mma.sync.aligned.m16n8k16.row.col.f32.f16.f16.f32 "
                 "{%0,%1,%2,%3}, {%4,%5,%6,%7}, {%8,%9}, {%0,%1,%2,%3};"
                 : "+f"(c[0]), "+f"(c[1]), "+f"(c[2]), "+f"(c[3])
                 : "r"(a[0]), "r"(a[1]), "r"(a[2]), "r"(a[3]),
                   "r"(b0), "r"(b1));
}

__device__ __forceinline__ uint32_t sw128(uint32_t off) {
    return off ^ ((off >> 3) & 0x70);
}

// ---------------------------------------------------------------------------
// Kernel 1: split x[4096,1024] fp32 -> A' = [x_hi | x_lo] fp16
// ---------------------------------------------------------------------------
__global__ void split_x_kernel(const float* __restrict__ x) {
    int t = blockIdx.x * blockDim.x + threadIdx.x;
    int idx4 = t << 2;
    int b = idx4 >> 10;
    int j = idx4 & (N_DIM - 1);
    float4 v = *reinterpret_cast<const float4*>(x + idx4);

    __half h0 = __float2half_rn(v.x);
    __half h1 = __float2half_rn(v.y);
    __half h2 = __float2half_rn(v.z);
    __half h3 = __float2half_rn(v.w);
    __half l0 = __float2half_rn(v.x - __half2float(h0));
    __half l1 = __float2half_rn(v.y - __half2float(h1));
    __half l2 = __float2half_rn(v.z - __half2float(h2));
    __half l3 = __float2half_rn(v.w - __half2float(h3));

    ushort4 hv, lv;
    hv.x = __half_as_ushort(h0); hv.y = __half_as_ushort(h1);
    hv.z = __half_as_ushort(h2); hv.w = __half_as_ushort(h3);
    lv.x = __half_as_ushort(l0); lv.y = __half_as_ushort(l1);
    lv.z = __half_as_ushort(l2); lv.w = __half_as_ushort(l3);

    size_t base = (size_t)b * KA + j;
    *reinterpret_cast<ushort4*>(g_A + base)         = hv;   // seg0: x_hi
    *reinterpret_cast<ushort4*>(g_A + base + N_DIM) = lv;   // seg1: x_lo
}

// ---------------------------------------------------------------------------
// Kernel 2: filters[e,i,j] = sum_p params[p,e]*T[p,i,j] -> W_hi fp16,
//           B'[c=i*16+e, k] K-major rows
// ---------------------------------------------------------------------------
__global__ void build_filters_kernel(const float* __restrict__ params,
                                     const float* __restrict__ T) {
    __shared__ float sp[P_DIM * E_DIM];
    for (int s = threadIdx.x; s < P_DIM * E_DIM; s += blockDim.x) sp[s] = params[s];
    __syncthreads();

    int t = blockIdx.x * blockDim.x + threadIdx.x;
    int idx4 = t << 2;
    int i = idx4 >> 10;
    int j = idx4 & (N_DIM - 1);

    float4 acc[E_DIM];
#pragma unroll
    for (int e = 0; e < E_DIM; e++) acc[e] = make_float4(0.f, 0.f, 0.f, 0.f);

    for (int p = 0; p < P_DIM; p++) {
        float4 tv = *reinterpret_cast<const float4*>(T + ((size_t)p << 20) + idx4);
#pragma unroll
        for (int e = 0; e < E_DIM; e++) {
            float w = sp[p * E_DIM + e];
            acc[e].x = fmaf(tv.x, w, acc[e].x);
            acc[e].y = fmaf(tv.y, w, acc[e].y);
            acc[e].z = fmaf(tv.z, w, acc[e].z);
            acc[e].w = fmaf(tv.w, w, acc[e].w);
        }
    }

#pragma unroll
    for (int e = 0; e < E_DIM; e++) {
        int c = i * E_DIM + e;
        ushort4 hv;
        hv.x = __half_as_ushort(__float2half_rn(acc[e].x));
        hv.y = __half_as_ushort(__float2half_rn(acc[e].y));
        hv.z = __half_as_ushort(__float2half_rn(acc[e].z));
        hv.w = __half_as_ushort(__float2half_rn(acc[e].w));
        *reinterpret_cast<ushort4*>(g_Bm + (size_t)c * KB + j) = hv;
    }
}

// ---------------------------------------------------------------------------
// Kernel 3: GEMM out[b,c] = sum_k A'[b,k]*W_hi[c,k mod 1024], swish, fp32 out.
// CTA 128x256. Each iteration: 1 B chunk (64 cols) + A_hi & A_lo chunks;
// B register fragments reused across both A passes. 3-stage cp.async pipeline.
// 16 warps: warp grid 4(M) x 4(N), warp tile 32x64.
// ---------------------------------------------------------------------------
__device__ __forceinline__ void load_chunk(uint32_t sbase, int tid, int kc,
                                           const __half* __restrict__ Ag,
                                           const __half* __restrict__ Bg) {
    int st = kc % NSTAGES;
    uint32_t stA = sbase + st * STAGE_BYTES;          // A_hi ; A_lo at +16KB
    uint32_t stB = stA + STAGE_A_BYTES;
    const __half* ga = Ag + kc * BK;                  // A_hi ; A_lo at +KB
    const __half* gb = Bg + kc * BK;
#pragma unroll
    for (int i = 0; i < 2; i++) {               // A_hi: 128 rows x 8 vec16
        int v = i * NTHREADS + tid;
        int row = v >> 3, c16 = v & 7;
        uint32_t off = (uint32_t)(row * 128 + c16 * 16);
        cp_async16(stA + sw128(off), ga + (size_t)row * KA + (c16 << 3));
    }
#pragma unroll
    for (int i = 0; i < 2; i++) {               // A_lo: 128 rows x 8 vec16
        int v = i * NTHREADS + tid;
        int row = v >> 3, c16 = v & 7;
        uint32_t off = (uint32_t)(row * 128 + c16 * 16);
        cp_async16(stA + STAGE_AH_BYTES + sw128(off),
                   ga + KB + (size_t)row * KA + (c16 << 3));
    }
#pragma unroll
    for (int i = 0; i < 4; i++) {               // B: 256 rows x 8 vec16
        int v = i * NTHREADS + tid;
        int row = v >> 3, c16 = v & 7;
        uint32_t off = (uint32_t)(row * 128 + c16 * 16);
        cp_async16(stB + sw128(off), gb + (size_t)row * KB + (c16 << 3));
    }
    asm volatile("cp.async.commit_group;\n" ::: "memory");
}

__global__ void __launch_bounds__(NTHREADS, 1)
gemm_swish_kernel(float* __restrict__ out) {
    extern __shared__ char dsm[];
    const int tid  = threadIdx.x;
    const int wid  = tid >> 5;
    const int lane = tid & 31;
    const int warp_m = wid & 3;     // 0..3 -> 32-row slices
    const int warp_n = wid >> 2;    // 0..3 -> 64-col slices

    uint32_t sbase = cvta_shared(dsm);

    const size_t m_base = (size_t)blockIdx.x * BM;
    const size_t n_base = (size_t)blockIdx.y * BN;
    const __half* __restrict__ Ag = g_A  + m_base * KA;
    const __half* __restrict__ Bg = g_Bm + n_base * KB;

    float acc[2][8][4];
#pragma unroll
    for (int mi = 0; mi < 2; mi++)
#pragma unroll
        for (int ni = 0; ni < 8; ni++)
#pragma unroll
            for (int c = 0; c < 4; c++) acc[mi][ni][c] = 0.0f;

    // prologue: stages 0,1 in flight
    load_chunk(sbase, tid, 0, Ag, Bg);
    load_chunk(sbase, tid, 1, Ag, Bg);

    // per-lane ldmatrix row offsets
    const int a_row = warp_m * 32 + (lane & 15);                      // + mi*16
    const int a_kh  = (lane >> 4) << 4;                               // 0/16 B
    const int b_row = warp_n * 64 + (lane & 7) + ((lane & 16) >> 1);  // + ni*16
    const int b_kh  = (lane & 8) << 1;                                // 0/16 B

    for (int k = 0; k < NCH; k++) {
        if (k < NCH - 1) asm volatile("cp.async.wait_group 1;\n" ::: "memory");
        else             asm volatile("cp.async.wait_group 0;\n" ::: "memory");
        __syncthreads();

        if (k + 2 < NCH) load_chunk(sbase, tid, k + 2, Ag, Bg);

        int st = k % NSTAGES;
        uint32_t stA = sbase + st * STAGE_BYTES;
        uint32_t stB = stA + STAGE_A_BYTES;

#pragma unroll
        for (int kk = 0; kk < 4; kk++) {        // 4 x k16 per 64-chunk
            uint32_t b[4][4];
#pragma unroll
            for (int ni = 0; ni < 4; ni++) {
                uint32_t off = (uint32_t)((b_row + ni * 16) * 128 + kk * 32 + b_kh);
                ldmatrix_x4(b[ni], stB + sw128(off));
            }
#pragma unroll
            for (int pass = 0; pass < 2; pass++) {   // A_hi then A_lo, same B
                uint32_t a[2][4];
#pragma unroll
                for (int mi = 0; mi < 2; mi++) {
                    uint32_t off = (uint32_t)((a_row + mi * 16) * 128 + kk * 32 + a_kh);
                    ldmatrix_x4(a[mi], stA + pass * STAGE_AH_BYTES + sw128(off));
                }
#pragma unroll
                for (int mi = 0; mi < 2; mi++)
#pragma unroll
                    for (int n8 = 0; n8 < 8; n8++)
                        mma_f16(acc[mi][n8], a[mi],
                                b[n8 >> 1][(n8 & 1) * 2],
                                b[n8 >> 1][(n8 & 1) * 2 + 1]);
            }
        }
    }

    // epilogue: swish + store fp32
    const int quad = lane >> 2;        // 0..7: row within 8-row group
    const int tcol = (lane & 3) * 2;   // col pair
#pragma unroll
    for (int mi = 0; mi < 2; mi++) {
        size_t row0 = m_base + warp_m * 32 + mi * 16 + quad;
#pragma unroll
        for (int n8 = 0; n8 < 8; n8++) {
            size_t col = n_base + warp_n * 64 + n8 * 8 + tcol;
            float a0 = acc[mi][n8][0], a1 = acc[mi][n8][1];
            float a2 = acc[mi][n8][2], a3 = acc[mi][n8][3];
            float2 v0, v1;
            v0.x = a0 / (1.0f + __expf(-a0));
            v0.y = a1 / (1.0f + __expf(-a1));
            v1.x = a2 / (1.0f + __expf(-a2));
            v1.y = a3 / (1.0f + __expf(-a3));
            *reinterpret_cast<float2*>(out + row0 * C_DIM + col)       = v0;
            *reinterpret_cast<float2*>(out + (row0 + 8) * C_DIM + col) = v1;
        }
    }
}

// ---------------------------------------------------------------------------
// Launch
// ---------------------------------------------------------------------------
extern "C" void kernel_launch(void* const* d_in, const int* in_sizes, int n_in,
                              void* d_out, int out_size) {
    const float* x = nullptr;
    const float* params = nullptr;
    const float* T = nullptr;
    for (int i = 0; i < n_in; i++) {
        if (in_sizes[i] == B_ROWS * N_DIM)             x      = (const float*)d_in[i];
        else if (in_sizes[i] == P_DIM * E_DIM)         params = (const float*)d_in[i];
        else if (in_sizes[i] == P_DIM * N_DIM * N_DIM) T      = (const float*)d_in[i];
    }
    float* out = (float*)d_out;

    split_x_kernel<<<(B_ROWS * N_DIM) / (256 * 4), 256>>>(x);
    build_filters_kernel<<<(N_DIM * N_DIM) / (256 * 4), 256>>>(params, T);

    cudaFuncSetAttribute(gemm_swish_kernel,
                         cudaFuncAttributeMaxDynamicSharedMemorySize, SMEM_DYN);
    gemm_swish_kernel<<<dim3(B_ROWS / BM, C_DIM / BN), NTHREADS, SMEM_DYN>>>(out);
}

// round 4
// speedup vs baseline: 2.2914x; 1.6240x over previous
#include <cuda_runtime.h>
#include <cuda_fp16.h>
#include <cstdint>

// ---------------------------------------------------------------------------
// Problem constants
// ---------------------------------------------------------------------------
#define B_ROWS 4096
#define N_DIM  1024
#define P_DIM  32
#define E_DIM  16
#define C_DIM  (N_DIM * E_DIM)   /* 16384 output columns (i*16+e) */
#define KDIM   1024              /* single-term fp16 GEMM K */

// GEMM tiling (mma.sync path — tcgen05 unavailable on compute_103 vtarget)
#define BM 128
#define BN 256
#define BK 64                        /* fp16 elems per K-chunk (128B rows) */
#define NCH (KDIM / BK)              /* 16 */
#define NSTAGES 4
#define STAGE_A_BYTES (BM * 128)     /* 16 KB */
#define STAGE_B_BYTES (BN * 128)     /* 32 KB */
#define STAGE_BYTES (STAGE_A_BYTES + STAGE_B_BYTES)   /* 48 KB */
#define SMEM_DYN (NSTAGES * STAGE_BYTES)              /* 192 KB */
#define NTHREADS 512

// ---------------------------------------------------------------------------
// Device scratch (allocation-free rule: __device__ globals)
// ---------------------------------------------------------------------------
__device__ __align__(16) __half g_A[(size_t)B_ROWS * KDIM];   // 8 MB
__device__ __align__(16) __half g_Bm[(size_t)C_DIM * KDIM];   // 32 MB

// ---------------------------------------------------------------------------
// PTX helpers (baseline features only — must compile for compute_103)
// ---------------------------------------------------------------------------
__device__ __forceinline__ uint32_t cvta_shared(const void* p) {
    return (uint32_t)__cvta_generic_to_shared(p);
}

__device__ __forceinline__ void cp_async16(uint32_t dst, const void* src) {
    asm volatile("cp.async.cg.shared.global [%0], [%1], 16;\n"
                 :: "r"(dst), "l"(src) : "memory");
}

__device__ __forceinline__ void ldmatrix_x4(uint32_t* d, uint32_t addr) {
    asm volatile("ldmatrix.sync.aligned.m8n8.x4.shared.b16 {%0,%1,%2,%3}, [%4];"
                 : "=r"(d[0]), "=r"(d[1]), "=r"(d[2]), "=r"(d[3]) : "r"(addr));
}

__device__ __forceinline__ void mma_f16(float* c, const uint32_t* a,
                                        uint32_t b0, uint32_t b1) {
    asm volatile("mma.sync.aligned.m16n8k16.row.col.f32.f16.f16.f32 "
                 "{%0,%1,%2,%3}, {%4,%5,%6,%7}, {%8,%9}, {%0,%1,%2,%3};"
                 : "+f"(c[0]), "+f"(c[1]), "+f"(c[2]), "+f"(c[3])
                 : "r"(a[0]), "r"(a[1]), "r"(a[2]), "r"(a[3]),
                   "r"(b0), "r"(b1));
}

__device__ __forceinline__ uint32_t sw128(uint32_t off) {
    return off ^ ((off >> 3) & 0x70);
}

// ---------------------------------------------------------------------------
// Kernel 1: convert x[4096,1024] fp32 -> fp16
// ---------------------------------------------------------------------------
__global__ void convert_x_kernel(const float* __restrict__ x) {
    int t = blockIdx.x * blockDim.x + threadIdx.x;
    int idx4 = t << 2;
    float4 v = *reinterpret_cast<const float4*>(x + idx4);
    ushort4 hv;
    hv.x = __half_as_ushort(__float2half_rn(v.x));
    hv.y = __half_as_ushort(__float2half_rn(v.y));
    hv.z = __half_as_ushort(__float2half_rn(v.z));
    hv.w = __half_as_ushort(__float2half_rn(v.w));
    *reinterpret_cast<ushort4*>(g_A + idx4) = hv;
}

// ---------------------------------------------------------------------------
// Kernel 2: filters[e,i,j] = sum_p params[p,e]*T[p,i,j] -> fp16,
//           B'[c=i*16+e, k] K-major rows
// ---------------------------------------------------------------------------
__global__ void build_filters_kernel(const float* __restrict__ params,
                                     const float* __restrict__ T) {
    __shared__ float sp[P_DIM * E_DIM];
    for (int s = threadIdx.x; s < P_DIM * E_DIM; s += blockDim.x) sp[s] = params[s];
    __syncthreads();

    int t = blockIdx.x * blockDim.x + threadIdx.x;
    int idx4 = t << 2;
    int i = idx4 >> 10;
    int j = idx4 & (N_DIM - 1);

    float4 acc[E_DIM];
#pragma unroll
    for (int e = 0; e < E_DIM; e++) acc[e] = make_float4(0.f, 0.f, 0.f, 0.f);

    for (int p = 0; p < P_DIM; p++) {
        float4 tv = *reinterpret_cast<const float4*>(T + ((size_t)p << 20) + idx4);
#pragma unroll
        for (int e = 0; e < E_DIM; e++) {
            float w = sp[p * E_DIM + e];
            acc[e].x = fmaf(tv.x, w, acc[e].x);
            acc[e].y = fmaf(tv.y, w, acc[e].y);
            acc[e].z = fmaf(tv.z, w, acc[e].z);
            acc[e].w = fmaf(tv.w, w, acc[e].w);
        }
    }

#pragma unroll
    for (int e = 0; e < E_DIM; e++) {
        int c = i * E_DIM + e;
        ushort4 hv;
        hv.x = __half_as_ushort(__float2half_rn(acc[e].x));
        hv.y = __half_as_ushort(__float2half_rn(acc[e].y));
        hv.z = __half_as_ushort(__float2half_rn(acc[e].z));
        hv.w = __half_as_ushort(__float2half_rn(acc[e].w));
        *reinterpret_cast<ushort4*>(g_Bm + (size_t)c * KDIM + j) = hv;
    }
}

// ---------------------------------------------------------------------------
// Kernel 3: GEMM out[b,c] = sum_k A[b,k]*W[c,k], swish, fp32 out.
// CTA 128x256, K chunks of 64, 4-stage cp.async pipeline, mma.sync fp16.
// 16 warps: warp grid 4(M) x 4(N), warp tile 32x64.
// ---------------------------------------------------------------------------
__device__ __forceinline__ void load_chunk(uint32_t sbase, int tid, int kc,
                                           const __half* __restrict__ Ag,
                                           const __half* __restrict__ Bg) {
    int st = kc & (NSTAGES - 1);
    uint32_t stA = sbase + st * STAGE_BYTES;
    uint32_t stB = stA + STAGE_A_BYTES;
    const __half* ga = Ag + kc * BK;
    const __half* gb = Bg + kc * BK;
#pragma unroll
    for (int i = 0; i < 2; i++) {               // A: 128 rows x 8 vec16 = 1024
        int v = i * NTHREADS + tid;
        int row = v >> 3, c16 = v & 7;
        uint32_t off = (uint32_t)(row * 128 + c16 * 16);
        cp_async16(stA + sw128(off), ga + (size_t)row * KDIM + (c16 << 3));
    }
#pragma unroll
    for (int i = 0; i < 4; i++) {               // B: 256 rows x 8 vec16 = 2048
        int v = i * NTHREADS + tid;
        int row = v >> 3, c16 = v & 7;
        uint32_t off = (uint32_t)(row * 128 + c16 * 16);
        cp_async16(stB + sw128(off), gb + (size_t)row * KDIM + (c16 << 3));
    }
    asm volatile("cp.async.commit_group;\n" ::: "memory");
}

__global__ void __launch_bounds__(NTHREADS, 1)
gemm_swish_kernel(float* __restrict__ out) {
    extern __shared__ char dsm[];
    const int tid  = threadIdx.x;
    const int wid  = tid >> 5;
    const int lane = tid & 31;
    const int warp_m = wid & 3;     // 0..3 -> 32-row slices
    const int warp_n = wid >> 2;    // 0..3 -> 64-col slices

    uint32_t sbase = cvta_shared(dsm);

    const size_t m_base = (size_t)blockIdx.x * BM;
    const size_t n_base = (size_t)blockIdx.y * BN;
    const __half* __restrict__ Ag = g_A  + m_base * KDIM;
    const __half* __restrict__ Bg = g_Bm + n_base * KDIM;

    float acc[2][8][4];
#pragma unroll
    for (int mi = 0; mi < 2; mi++)
#pragma unroll
        for (int ni = 0; ni < 8; ni++)
#pragma unroll
            for (int c = 0; c < 4; c++) acc[mi][ni][c] = 0.0f;

    // prologue: stages 0..2 in flight
    load_chunk(sbase, tid, 0, Ag, Bg);
    load_chunk(sbase, tid, 1, Ag, Bg);
    load_chunk(sbase, tid, 2, Ag, Bg);

    // per-lane ldmatrix row offsets
    const int a_row = warp_m * 32 + (lane & 15);                      // + mi*16
    const int a_kh  = (lane >> 4) << 4;                               // 0/16 B
    const int b_row = warp_n * 64 + (lane & 7) + ((lane & 16) >> 1);  // + ni*16
    const int b_kh  = (lane & 8) << 1;                                // 0/16 B

    for (int k = 0; k < NCH; k++) {
        if (k < NCH - 2)       asm volatile("cp.async.wait_group 2;\n" ::: "memory");
        else if (k == NCH - 2) asm volatile("cp.async.wait_group 1;\n" ::: "memory");
        else                   asm volatile("cp.async.wait_group 0;\n" ::: "memory");
        __syncthreads();

        if (k + 3 < NCH) load_chunk(sbase, tid, k + 3, Ag, Bg);

        int st = k & (NSTAGES - 1);
        uint32_t stA = sbase + st * STAGE_BYTES;
        uint32_t stB = stA + STAGE_A_BYTES;

#pragma unroll
        for (int kk = 0; kk < 4; kk++) {        // 4 x k16 per 64-chunk
            uint32_t b[4][4];
#pragma unroll
            for (int ni = 0; ni < 4; ni++) {
                uint32_t off = (uint32_t)((b_row + ni * 16) * 128 + kk * 32 + b_kh);
                ldmatrix_x4(b[ni], stB + sw128(off));
            }
            uint32_t a[2][4];
#pragma unroll
            for (int mi = 0; mi < 2; mi++) {
                uint32_t off = (uint32_t)((a_row + mi * 16) * 128 + kk * 32 + a_kh);
                ldmatrix_x4(a[mi], stA + sw128(off));
            }
#pragma unroll
            for (int mi = 0; mi < 2; mi++)
#pragma unroll
                for (int n8 = 0; n8 < 8; n8++)
                    mma_f16(acc[mi][n8], a[mi],
                            b[n8 >> 1][(n8 & 1) * 2],
                            b[n8 >> 1][(n8 & 1) * 2 + 1]);
        }
    }

    // epilogue: swish + store fp32
    const int quad = lane >> 2;        // 0..7: row within 8-row group
    const int tcol = (lane & 3) * 2;   // col pair
#pragma unroll
    for (int mi = 0; mi < 2; mi++) {
        size_t row0 = m_base + warp_m * 32 + mi * 16 + quad;
#pragma unroll
        for (int n8 = 0; n8 < 8; n8++) {
            size_t col = n_base + warp_n * 64 + n8 * 8 + tcol;
            float a0 = acc[mi][n8][0], a1 = acc[mi][n8][1];
            float a2 = acc[mi][n8][2], a3 = acc[mi][n8][3];
            float2 v0, v1;
            v0.x = a0 / (1.0f + __expf(-a0));
            v0.y = a1 / (1.0f + __expf(-a1));
            v1.x = a2 / (1.0f + __expf(-a2));
            v1.y = a3 / (1.0f + __expf(-a3));
            *reinterpret_cast<float2*>(out + row0 * C_DIM + col)       = v0;
            *reinterpret_cast<float2*>(out + (row0 + 8) * C_DIM + col) = v1;
        }
    }
}

// ---------------------------------------------------------------------------
// Launch
// ---------------------------------------------------------------------------
extern "C" void kernel_launch(void* const* d_in, const int* in_sizes, int n_in,
                              void* d_out, int out_size) {
    const float* x = nullptr;
    const float* params = nullptr;
    const float* T = nullptr;
    for (int i = 0; i < n_in; i++) {
        if (in_sizes[i] == B_ROWS * N_DIM)             x      = (const float*)d_in[i];
        else if (in_sizes[i] == P_DIM * E_DIM)         params = (const float*)d_in[i];
        else if (in_sizes[i] == P_DIM * N_DIM * N_DIM) T      = (const float*)d_in[i];
    }
    float* out = (float*)d_out;

    convert_x_kernel<<<(B_ROWS * N_DIM) / (256 * 4), 256>>>(x);
    build_filters_kernel<<<(N_DIM * N_DIM) / (256 * 4), 256>>>(params, T);

    cudaFuncSetAttribute(gemm_swish_kernel,
                         cudaFuncAttributeMaxDynamicSharedMemorySize, SMEM_DYN);
    gemm_swish_kernel<<<dim3(B_ROWS / BM, C_DIM / BN), NTHREADS, SMEM_DYN>>>(out);
}